// round 2
// baseline (speedup 1.0000x reference)
#include <cuda_runtime.h>
#include <cstdint>

#define H        768
#define CK       48                 // K-chunk size
#define NCHUNK   (H / CK)           // 16
#define TROWS    128                // rows per tile == threads per block
#define STRIDE   52                 // floats per row in smem (48 + 4 pad, keeps 16B align + conflict-free)
#define BUF_FLOATS (TROWS * STRIDE) // per-buffer floats
#define BUF_BYTES  (BUF_FLOATS * 4)

// Packed weights: c_W4[k][q] is a float4 covering channel-pairs 2q and 2q+1
// (i.e. channels 4q..4q+3). 18 padded channels => 9 pairs => 4 full float4 + pair 8.
__constant__ float4 c_W4[H][5];
__constant__ float  c_bias[20];

__device__ float2       g_pack[H * 10];
__device__ float        g_biasStage[20];
__device__ unsigned int g_ticket;

// ---------------------------------------------------------------------------
// Prep: transpose/pack weights into [k][pair] layout + biases, reset ticket.
// Channel order: a0,a1 | b0..b3 | c1_0,c1_1 | c2_0..2 | c3_0..3 | c4_0,c4_1 | pad
// ---------------------------------------------------------------------------
__global__ void prep_kernel(
    const float* __restrict__ Wa,  const float* __restrict__ ba,
    const float* __restrict__ Wb,  const float* __restrict__ bb,
    const float* __restrict__ Wc1, const float* __restrict__ bc1,
    const float* __restrict__ Wc2, const float* __restrict__ bc2,
    const float* __restrict__ Wc3, const float* __restrict__ bc3,
    const float* __restrict__ Wc4, const float* __restrict__ bc4)
{
    int id = blockIdx.x * blockDim.x + threadIdx.x;
    if (id == 0) g_ticket = 0u;

    auto getw = [&](int ch, int k) -> float {
        if (ch < 2)  return Wa [ ch        * H + k];
        if (ch < 6)  return Wb [(ch - 2)  * H + k];
        if (ch < 8)  return Wc1[(ch - 6)  * H + k];
        if (ch < 11) return Wc2[(ch - 8)  * H + k];
        if (ch < 15) return Wc3[(ch - 11) * H + k];
        if (ch < 17) return Wc4[(ch - 15) * H + k];
        return 0.0f;
    };

    if (id < H * 10) {
        int k = id / 10, p = id % 10;
        g_pack[k * 10 + p] = make_float2(getw(2 * p, k), getw(2 * p + 1, k));
    }
    if (id < 20) {
        int ch = id; float b;
        if      (ch < 2)  b = ba [ch];
        else if (ch < 6)  b = bb [ch - 2];
        else if (ch < 8)  b = bc1[ch - 6];
        else if (ch < 11) b = bc2[ch - 8];
        else if (ch < 15) b = bc3[ch - 11];
        else if (ch < 17) b = bc4[ch - 15];
        else              b = 0.0f;
        g_biasStage[ch] = b;
    }
}

// ---------------------------------------------------------------------------
// Packed fp32x2 FMA (SASS FFMA2) — 2 fp32 FMAs per instruction.
// ---------------------------------------------------------------------------
__device__ __forceinline__ void ffma2(float2& d, const float2 a, const float2 b)
{
    asm("fma.rn.f32x2 %0, %1, %2, %0;"
        : "+l"(reinterpret_cast<unsigned long long&>(d))
        : "l"(reinterpret_cast<const unsigned long long&>(a)),
          "l"(reinterpret_cast<const unsigned long long&>(b)));
}

__device__ __forceinline__ void cp16(uint32_t saddr, const void* gptr)
{
    asm volatile("cp.async.cg.shared.global [%0], [%1], 16;" :: "r"(saddr), "l"(gptr));
}
__device__ __forceinline__ void cp_commit() { asm volatile("cp.async.commit_group;"); }
template <int N>
__device__ __forceinline__ void cp_wait()   { asm volatile("cp.async.wait_group %0;" :: "n"(N)); }

// ---------------------------------------------------------------------------
// Main kernel: persistent CTAs, ticket over 128-row tiles.
// One thread == one row; 9 f32x2 channel-pair accumulators; W via LDCU.
// ---------------------------------------------------------------------------
extern __shared__ float xs[];   // 2 * BUF_FLOATS

__global__ void __launch_bounds__(TROWS)
main_kernel(const float* __restrict__ x, float* __restrict__ out, int B, int ntiles)
{
    const int t = threadIdx.x;
    const uint32_t sbase = (uint32_t)__cvta_generic_to_shared(xs);
    __shared__ unsigned s_tile;

    for (;;) {
        if (t == 0) s_tile = atomicAdd(&g_ticket, 1u);
        __syncthreads();
        const unsigned tile = s_tile;
        if (tile >= (unsigned)ntiles) break;

        const int  row0 = (int)tile * TROWS;
        const float* gx = x + (size_t)row0 * H;

        float2 acc[9];
        #pragma unroll
        for (int p = 0; p < 9; ++p) acc[p] = make_float2(0.f, 0.f);

        // --- stage chunk 0 ---
        {
            #pragma unroll
            for (int i = 0; i < 12; ++i) {
                int idx = t + TROWS * i;          // 0 .. 1535
                int row = idx / 12, v = idx % 12; // 12 float4 per row per chunk
                if (row0 + row < B)
                    cp16(sbase + row * (STRIDE * 4) + v * 16,
                         gx + (size_t)row * H + v * 4);
            }
            cp_commit();
        }

        for (int c = 0; c < NCHUNK; ++c) {
            // prefetch next chunk into other buffer
            if (c + 1 < NCHUNK) {
                const int nb = (c + 1) & 1;
                const float* gsrc = gx + (c + 1) * CK;
                #pragma unroll
                for (int i = 0; i < 12; ++i) {
                    int idx = t + TROWS * i;
                    int row = idx / 12, v = idx % 12;
                    if (row0 + row < B)
                        cp16(sbase + nb * BUF_BYTES + row * (STRIDE * 4) + v * 16,
                             gsrc + (size_t)row * H + v * 4);
                }
                cp_commit();
                cp_wait<1>();
            } else {
                cp_wait<0>();
            }
            __syncthreads();

            // compute chunk c
            const float4* xr = (const float4*)(xs + (c & 1) * BUF_FLOATS + t * STRIDE);
            const int kchunk = c * CK;
            #pragma unroll 4
            for (int kk = 0; kk < 12; ++kk) {
                float4 xv = xr[kk];
                int kb = kchunk + kk * 4;
                #pragma unroll
                for (int j = 0; j < 4; ++j) {
                    float xk = (j == 0) ? xv.x : (j == 1) ? xv.y : (j == 2) ? xv.z : xv.w;
                    float2 xd = make_float2(xk, xk);
                    const float4* wk = c_W4[kb + j];    // warp-uniform address -> LDCU
                    #pragma unroll
                    for (int p = 0; p < 4; ++p) {
                        float4 w = wk[p];
                        ffma2(acc[2 * p],     xd, make_float2(w.x, w.y));
                        ffma2(acc[2 * p + 1], xd, make_float2(w.z, w.w));
                    }
                    float4 w4 = wk[4];
                    ffma2(acc[8], xd, make_float2(w4.x, w4.y));
                }
            }
            __syncthreads();   // buffer (c&1) may be overwritten next iteration
        }

        // --- epilogue: bias, routing, masked stores ---
        const int r = row0 + t;
        if (r < B) {
            float v[18];
            #pragma unroll
            for (int p = 0; p < 9; ++p) {
                v[2 * p]     = acc[p].x + c_bias[2 * p];
                v[2 * p + 1] = acc[p].y + c_bias[2 * p + 1];
            }
            const bool active = v[1] > v[0];          // argmax([a0,a1]) != 0 (tie -> 0)

            ((float2*)out)[r] = make_float2(v[0], v[1]);   // out_a

            int pb = 0; float best = v[2];
            if (v[3] > best) { pb = 1; best = v[3]; }
            if (v[4] > best) { pb = 2; best = v[4]; }
            if (v[5] > best) { pb = 3; best = v[5]; }

            float* ob = out + 2 * (size_t)B + 5 * (size_t)r;   // out_b
            ob[0] = 0.0f;
            #pragma unroll
            for (int j = 0; j < 4; ++j) ob[j + 1] = active ? v[2 + j] : 0.0f;

            float* oc = out + 7 * (size_t)B + 11 * (size_t)r;  // out_c
            #pragma unroll
            for (int j = 0; j < 11; ++j) {
                int hd = (j < 2) ? 0 : (j < 5) ? 1 : (j < 9) ? 2 : 3;
                oc[j] = (active && hd == pb) ? v[6 + j] : 0.0f;
            }
        }
    }
}

// ---------------------------------------------------------------------------
extern "C" void kernel_launch(void* const* d_in, const int* in_sizes, int n_in,
                              void* d_out, int out_size)
{
    const float* x = (const float*)d_in[0];
    const int B = in_sizes[0] / H;

    prep_kernel<<<30, 256>>>(
        (const float*)d_in[1],  (const float*)d_in[2],
        (const float*)d_in[3],  (const float*)d_in[4],
        (const float*)d_in[5],  (const float*)d_in[6],
        (const float*)d_in[7],  (const float*)d_in[8],
        (const float*)d_in[9],  (const float*)d_in[10],
        (const float*)d_in[11], (const float*)d_in[12]);

    void* packAddr = nullptr;  cudaGetSymbolAddress(&packAddr, g_pack);
    void* biasAddr = nullptr;  cudaGetSymbolAddress(&biasAddr, g_biasStage);
    cudaMemcpyToSymbolAsync(c_W4,  packAddr, sizeof(float2) * H * 10, 0,
                            cudaMemcpyDeviceToDevice, 0);
    cudaMemcpyToSymbolAsync(c_bias, biasAddr, sizeof(float) * 20, 0,
                            cudaMemcpyDeviceToDevice, 0);

    const int ntiles = (B + TROWS - 1) / TROWS;
    int grid = 148 * 3;
    if (grid > ntiles) grid = ntiles;

    const size_t smem = 2 * BUF_BYTES;
    cudaFuncSetAttribute(main_kernel, cudaFuncAttributeMaxDynamicSharedMemorySize, (int)smem);
    main_kernel<<<grid, TROWS, smem>>>(x, (float*)d_out, B, ntiles);
}